// round 8
// baseline (speedup 1.0000x reference)
#include <cuda_runtime.h>

#define B_ 8
#define M_ 2048
#define N_ 2048
#define R_ 32
#define SPLITK 4
#define KS (N_ / SPLITK)     // 512 per split
#define KT 32                // k-tile
#define BMT 256              // output-dim tile

#define L1C 10.24f
#define L2C 10.24f
#define EPSC 1e-16f

typedef unsigned long long ull;

// Scratch (device globals; no allocation allowed)
__device__ float g_ap[SPLITK * B_ * M_ * R_];   // split-K GEMM partials
__device__ float g_bp[16 * B_ * R_ * R_];       // split-K gram partials
__device__ float g_b[B_ * R_ * R_];             // reduced gram matrix

// ---- f32x2 helpers (Blackwell packed fp32 pipe: SASS FFMA2) ------------
__device__ __forceinline__ ull pk2(float a, float b) {
    ull r; asm("mov.b64 %0, {%1,%2};" : "=l"(r) : "f"(a), "f"(b)); return r;
}
__device__ __forceinline__ void unpk2(ull p, float& a, float& b) {
    asm("mov.b64 {%0,%1}, %2;" : "=f"(a), "=f"(b) : "l"(p));
}
__device__ __forceinline__ ull ffma2(ull a, ull b, ull c) {
    ull d; asm("fma.rn.f32x2 %0, %1, %2, %3;" : "=l"(d) : "l"(a), "l"(b), "l"(c)); return d;
}

// ---------------------------------------------------------------------------
// Gram partials: g_bp[p][b][r][s] over a 128-row slice. grid (16,B_), 256 thr.
// ---------------------------------------------------------------------------
#define GCHUNK 128
__global__ void gram_partial_kernel(const float* __restrict__ vin) {
    __shared__ float vs[GCHUNK][R_];
    int b = blockIdx.y;
    int p = blockIdx.x;
    int k0 = p * GCHUNK;
    int tid = threadIdx.x;

    const float4* src = (const float4*)(vin + ((size_t)b * N_ + k0) * R_);
    float4* dst = (float4*)&vs[0][0];
#pragma unroll
    for (int i = 0; i < 4; i++) dst[tid + 256 * i] = src[tid + 256 * i];
    __syncthreads();

    int r  = tid >> 3;
    int s4 = (tid & 7) * 4;
    float ax = 0.f, ay = 0.f, az = 0.f, aw = 0.f;
#pragma unroll 8
    for (int m = 0; m < GCHUNK; m++) {
        float vr = vs[m][r];
        float4 sv = *(const float4*)&vs[m][s4];
        ax += vr * sv.x; ay += vr * sv.y; az += vr * sv.z; aw += vr * sv.w;
    }
    float* o = g_bp + ((size_t)p * B_ + b) * (R_ * R_) + r * R_ + s4;
    o[0] = ax; o[1] = ay; o[2] = az; o[3] = aw;
}

__global__ void reduce_b_kernel() {
    int i = blockIdx.x * blockDim.x + threadIdx.x;
    if (i < B_ * R_ * R_) {
        float s = 0.f;
#pragma unroll
        for (int p = 0; p < 16; p++) s += g_bp[(size_t)p * (B_ * R_ * R_) + i];
        g_b[i] = s;
    }
}

// ---------------------------------------------------------------------------
// a = x @ v. Output-pair packing, BOTH operands pre-paired in smem:
//   xsT[k][m] transposed tile -> x pairs {x[2q],x[2q+1]} via natural LDS.64
//   vs2[k][r] = {v[k][r], v[k][r]} pre-broadcast at staging time
// Inner loop per k-step: 4 LDS.64(v2) + 4 LDS.64(x) + 16 FFMA2
//   = 24 issue slots per 32 FMA-pipe cycles.
// grid (M_/256, SPLITK, B_), 256 threads, 2 CTAs/SM.
// ---------------------------------------------------------------------------
__global__ void __launch_bounds__(256, 2)
gemm_xv_kernel(const float* __restrict__ x, const float* __restrict__ v) {
    __shared__ float xsT[KT][BMT + 2];   // stride 258: LDS.64-aligned, conflict-free reads
    __shared__ ull   vs2[KT][R_];        // pre-broadcast {v,v} pairs (8 KB)

    int b   = blockIdx.z;
    int ks  = blockIdx.y;
    int m0  = blockIdx.x * BMT;
    int tid = threadIdx.x;
    int ty  = tid >> 3;          // 0..31 -> rows ty*8 .. +7 (4 pairs)
    int tx  = tid & 7;           // cols tx*4 .. +3

    const float* xb = x + (size_t)b * M_ * N_ + (size_t)ks * KS;
    const float* vb = v + (size_t)b * N_ * R_ + (size_t)ks * KS * R_;

    int srow = tid >> 3;         // staging row base (0..31), +32*i
    int skc  = tid & 7;          // staging k-chunk (float4 granules)
    int vrow = tid >> 3;         // v staging row
    int vq   = tid & 7;          // v staging quad

    ull acc[4][4];
#pragma unroll
    for (int p = 0; p < 4; p++)
#pragma unroll
        for (int c = 0; c < 4; c++) acc[p][c] = 0ull;

    // prefetch tile 0
    float4 px[8], pv;
#pragma unroll
    for (int i = 0; i < 8; i++)
        px[i] = *(const float4*)(xb + (size_t)(m0 + srow + 32 * i) * N_ + skc * 4);
    pv = ((const float4*)vb)[tid];

    for (int t = 0; t < KS / KT; t++) {
        // stage x transposed (k-major); v pre-broadcast as {v,v}
#pragma unroll
        for (int i = 0; i < 8; i++) {
            int row = srow + 32 * i;
            xsT[skc * 4 + 0][row] = px[i].x;
            xsT[skc * 4 + 1][row] = px[i].y;
            xsT[skc * 4 + 2][row] = px[i].z;
            xsT[skc * 4 + 3][row] = px[i].w;
        }
        vs2[vrow][vq * 4 + 0] = pk2(pv.x, pv.x);
        vs2[vrow][vq * 4 + 1] = pk2(pv.y, pv.y);
        vs2[vrow][vq * 4 + 2] = pk2(pv.z, pv.z);
        vs2[vrow][vq * 4 + 3] = pk2(pv.w, pv.w);
        __syncthreads();

        // prefetch next tile (overlaps compute)
        if (t + 1 < KS / KT) {
            int kb = (t + 1) * KT;
#pragma unroll
            for (int i = 0; i < 8; i++)
                px[i] = *(const float4*)(xb + (size_t)(m0 + srow + 32 * i) * N_ + kb + skc * 4);
            pv = ((const float4*)(vb + (size_t)kb * R_))[tid];
        }

#pragma unroll
        for (int k = 0; k < KT; k++) {
            ull v0 = vs2[k][tx * 4 + 0];
            ull v1 = vs2[k][tx * 4 + 1];
            ull v2 = vs2[k][tx * 4 + 2];
            ull v3 = vs2[k][tx * 4 + 3];
#pragma unroll
            for (int p = 0; p < 4; p++) {
                ull xp = *(const ull*)&xsT[k][ty * 8 + 2 * p];
                acc[p][0] = ffma2(xp, v0, acc[p][0]);
                acc[p][1] = ffma2(xp, v1, acc[p][1]);
                acc[p][2] = ffma2(xp, v2, acc[p][2]);
                acc[p][3] = ffma2(xp, v3, acc[p][3]);
            }
        }
        __syncthreads();
    }

    float* ab = g_ap + ((size_t)(ks * B_ + b) * M_ + m0) * R_;
#pragma unroll
    for (int p = 0; p < 4; p++) {
        float4 e, h;
        unpk2(acc[p][0], e.x, h.x);
        unpk2(acc[p][1], e.y, h.y);
        unpk2(acc[p][2], e.z, h.z);
        unpk2(acc[p][3], e.w, h.w);
        *(float4*)(ab + (size_t)(ty * 8 + 2 * p) * R_ + tx * 4)     = e;
        *(float4*)(ab + (size_t)(ty * 8 + 2 * p + 1) * R_ + tx * 4) = h;
    }
}

// ---------------------------------------------------------------------------
// a2 = x^T @ u. Same 24/32 inner loop; x tile naturally reduce-major
// (STS.128 staging, no transpose). grid (N_/256, SPLITK, B_), 256 threads.
// ---------------------------------------------------------------------------
#define MT 32
__global__ void __launch_bounds__(256, 2)
gemm_xtu_kernel(const float* __restrict__ x, const float* __restrict__ u) {
    __shared__ float xs[MT][BMT];   // stride 256: pair reads conflict-free
    __shared__ ull   us2[MT][R_];   // pre-broadcast {u,u} pairs

    int b   = blockIdx.z;
    int ks  = blockIdx.y;
    int n0  = blockIdx.x * BMT;
    int tid = threadIdx.x;
    int ty  = tid >> 3;          // 0..31 -> n ty*8 .. +7 (4 pairs)
    int tx  = tid & 7;

    const float* xb = x + (size_t)b * M_ * N_ + (size_t)ks * KS * N_;
    const float* ub = u + (size_t)b * M_ * R_ + (size_t)ks * KS * R_;

    int smr = tid >> 6;          // staging m-row base (0..3), +4*i
    int snc = tid & 63;          // staging float4 column
    int urow = tid >> 3;
    int uq   = tid & 7;

    ull acc[4][4];
#pragma unroll
    for (int p = 0; p < 4; p++)
#pragma unroll
        for (int c = 0; c < 4; c++) acc[p][c] = 0ull;

    float4 px[8], pu;
#pragma unroll
    for (int i = 0; i < 8; i++)
        px[i] = *(const float4*)(xb + (size_t)(smr + 4 * i) * N_ + n0 + snc * 4);
    pu = ((const float4*)ub)[tid];

    for (int t = 0; t < KS / MT; t++) {
#pragma unroll
        for (int i = 0; i < 8; i++)
            *(float4*)&xs[smr + 4 * i][snc * 4] = px[i];
        us2[urow][uq * 4 + 0] = pk2(pu.x, pu.x);
        us2[urow][uq * 4 + 1] = pk2(pu.y, pu.y);
        us2[urow][uq * 4 + 2] = pk2(pu.z, pu.z);
        us2[urow][uq * 4 + 3] = pk2(pu.w, pu.w);
        __syncthreads();

        if (t + 1 < KS / MT) {
            int mb = (t + 1) * MT;
#pragma unroll
            for (int i = 0; i < 8; i++)
                px[i] = *(const float4*)(xb + (size_t)(mb + smr + 4 * i) * N_ + n0 + snc * 4);
            pu = ((const float4*)(ub + (size_t)mb * R_))[tid];
        }

#pragma unroll
        for (int k = 0; k < MT; k++) {
            ull u0 = us2[k][tx * 4 + 0];
            ull u1 = us2[k][tx * 4 + 1];
            ull u2 = us2[k][tx * 4 + 2];
            ull u3 = us2[k][tx * 4 + 3];
#pragma unroll
            for (int p = 0; p < 4; p++) {
                ull xp = *(const ull*)&xs[k][ty * 8 + 2 * p];
                acc[p][0] = ffma2(xp, u0, acc[p][0]);
                acc[p][1] = ffma2(xp, u1, acc[p][1]);
                acc[p][2] = ffma2(xp, u2, acc[p][2]);
                acc[p][3] = ffma2(xp, u3, acc[p][3]);
            }
        }
        __syncthreads();
    }

    float* ab = g_ap + ((size_t)(ks * B_ + b) * N_ + n0) * R_;
#pragma unroll
    for (int p = 0; p < 4; p++) {
        float4 e, h;
        unpk2(acc[p][0], e.x, h.x);
        unpk2(acc[p][1], e.y, h.y);
        unpk2(acc[p][2], e.z, h.z);
        unpk2(acc[p][3], e.w, h.w);
        *(float4*)(ab + (size_t)(ty * 8 + 2 * p) * R_ + tx * 4)     = e;
        *(float4*)(ab + (size_t)(ty * 8 + 2 * p + 1) * R_ + tx * 4) = h;
    }
}

// ---------------------------------------------------------------------------
// Per-row Gauss-Seidel CD; sums SPLITK partials of a on load.
// grid (M_/128, B_), 128 threads. r-loop NOT unrolled -> low regs, 2x occ.
// ---------------------------------------------------------------------------
__global__ void cd_kernel(const float* __restrict__ uin, float* __restrict__ uout,
                          float l1, float l2) {
    __shared__ float bs[R_][R_];
    __shared__ float inv[R_];
    int b   = blockIdx.y;
    int tid = threadIdx.x;
    {
        const float4* src = (const float4*)(g_b + (size_t)b * R_ * R_);
        float4* dst = (float4*)&bs[0][0];
        dst[tid] = src[tid];
        dst[tid + 128] = src[tid + 128];
    }
    __syncthreads();
    if (tid < R_) inv[tid] = 1.0f / (bs[tid][tid] + l2 + EPSC);

    int m = blockIdx.x * 128 + tid;
    const size_t stride = (size_t)B_ * M_ * R_;
    const float* a0 = g_ap + ((size_t)b * M_ + m) * R_;
    const float* ur = uin + ((size_t)b * M_ + m) * R_;
    float areg[R_], ureg[R_];
#pragma unroll
    for (int i = 0; i < 8; i++) {
        float4 t0 = *(const float4*)(a0 + i * 4);
        float4 t1 = *(const float4*)(a0 + stride + i * 4);
        float4 t2 = *(const float4*)(a0 + 2 * stride + i * 4);
        float4 t3 = *(const float4*)(a0 + 3 * stride + i * 4);
        areg[4*i+0] = (t0.x + t1.x) + (t2.x + t3.x);
        areg[4*i+1] = (t0.y + t1.y) + (t2.y + t3.y);
        areg[4*i+2] = (t0.z + t1.z) + (t2.z + t3.z);
        areg[4*i+3] = (t0.w + t1.w) + (t2.w + t3.w);
        float4 tu = *(const float4*)(ur + i * 4);
        ureg[4*i+0] = tu.x; ureg[4*i+1] = tu.y; ureg[4*i+2] = tu.z; ureg[4*i+3] = tu.w;
    }
    __syncthreads();

#pragma unroll 1
    for (int r = 0; r < R_; r++) {
        float brr = bs[r][r];
        float d0 = 0.f, d1 = 0.f, d2 = 0.f, d3 = 0.f;
#pragma unroll
        for (int k = 0; k < R_; k += 4) {
            d0 += ureg[k + 0] * bs[k + 0][r];
            d1 += ureg[k + 1] * bs[k + 1][r];
            d2 += ureg[k + 2] * bs[k + 2][r];
            d3 += ureg[k + 3] * bs[k + 3][r];
        }
        float dot = (d0 + d1) + (d2 + d3);
        float z = areg[r] - (dot - ureg[r] * brr);
        float num = (z > l1) ? (z - l1) : ((z < -l1) ? (z + l1) : 0.0f);
        ureg[r] = (num + EPSC) * inv[r];
    }

    float* outr = uout + ((size_t)b * M_ + m) * R_;
#pragma unroll
    for (int i = 0; i < 8; i++) {
        float4 o = {ureg[4*i+0], ureg[4*i+1], ureg[4*i+2], ureg[4*i+3]};
        *(float4*)(outr + i * 4) = o;
    }
}

// ---------------------------------------------------------------------------
extern "C" void kernel_launch(void* const* d_in, const int* in_sizes, int n_in,
                              void* d_out, int out_size) {
    const float* x = (const float*)d_in[0];
    const float* u = (const float*)d_in[1];
    const float* v = (const float*)d_in[2];
    float* uout = (float*)d_out;                       // [B, M, R]
    float* vout = uout + (size_t)B_ * M_ * R_;         // [B, N, R]

    dim3 gg(16, B_);
    dim3 gm(M_ / BMT, SPLITK, B_);
    dim3 gn(N_ / BMT, SPLITK, B_);
    dim3 gc(M_ / 128, B_);

    // Phase 1: update u using original v
    gram_partial_kernel<<<gg, 256>>>(v);
    reduce_b_kernel<<<32, 256>>>();
    gemm_xv_kernel<<<gm, 256>>>(x, v);
    cd_kernel<<<gc, 128>>>(u, uout, L1C, L2C);

    // Phase 2: update v using NEW u
    gram_partial_kernel<<<gg, 256>>>(uout);
    reduce_b_kernel<<<32, 256>>>();
    gemm_xtu_kernel<<<gn, 256>>>(x, uout);
    cd_kernel<<<gc, 128>>>(v, vout, L1C, L2C);
}

// round 11
// speedup vs baseline: 1.9540x; 1.9540x over previous
#include <cuda_runtime.h>
#include <cstdint>

#define B_ 8
#define M_ 2048
#define N_ 2048
#define R_ 32

#define L1C 10.24f
#define L2C 10.24f
#define EPSC 1e-16f

// Scratch (device globals; no allocation allowed)
__device__ float g_a[B_ * M_ * R_];        // x@v or x^T@u  [B, M, R]
__device__ float g_bp[16 * B_ * R_ * R_];  // gram partials
__device__ float g_b[B_ * R_ * R_];        // reduced gram

// ---- bf16 helpers -------------------------------------------------------
__device__ __forceinline__ uint32_t pack2bf(float lo, float hi) {   // mem order [lo,hi]
    uint32_t r; asm("cvt.rn.bf16x2.f32 %0, %1, %2;" : "=r"(r) : "f"(hi), "f"(lo)); return r;
}
__device__ __forceinline__ uint16_t cvt1(float x) {
    uint16_t h; asm("cvt.rn.bf16.f32 %0, %1;" : "=h"(h) : "f"(x)); return h;
}
__device__ __forceinline__ float bf2f(uint16_t h) {
    return __uint_as_float(((uint32_t)h) << 16);
}
// D += A*B  (m16n8k16, bf16 in, fp32 acc)
__device__ __forceinline__ void mma16816(float* c, const uint32_t* a, uint32_t b0, uint32_t b1) {
    asm volatile(
        "mma.sync.aligned.m16n8k16.row.col.f32.bf16.bf16.f32 "
        "{%0,%1,%2,%3}, {%4,%5,%6,%7}, {%8,%9}, {%0,%1,%2,%3};"
        : "+f"(c[0]), "+f"(c[1]), "+f"(c[2]), "+f"(c[3])
        : "r"(a[0]), "r"(a[1]), "r"(a[2]), "r"(a[3]), "r"(b0), "r"(b1));
}

// ======================= gram kernels =======================
#define GCHUNK 128
__global__ void gram_partial_kernel(const float* __restrict__ vin) {
    __shared__ float vs[GCHUNK][R_];
    int b = blockIdx.y, p = blockIdx.x, tid = threadIdx.x;
    const float4* src = (const float4*)(vin + ((size_t)b * N_ + p * GCHUNK) * R_);
    float4* dst = (float4*)&vs[0][0];
#pragma unroll
    for (int i = 0; i < 4; i++) dst[tid + 256 * i] = src[tid + 256 * i];
    __syncthreads();
    int r = tid >> 3, s4 = (tid & 7) * 4;
    float ax = 0.f, ay = 0.f, az = 0.f, aw = 0.f;
#pragma unroll 8
    for (int m = 0; m < GCHUNK; m++) {
        float vr = vs[m][r];
        float4 sv = *(const float4*)&vs[m][s4];
        ax += vr * sv.x; ay += vr * sv.y; az += vr * sv.z; aw += vr * sv.w;
    }
    float* o = g_bp + ((size_t)p * B_ + b) * (R_ * R_) + r * R_ + s4;
    o[0] = ax; o[1] = ay; o[2] = az; o[3] = aw;
}

__global__ void reduce_b_kernel() {
    int i = blockIdx.x * blockDim.x + threadIdx.x;
    if (i < B_ * R_ * R_) {
        float s = 0.f;
#pragma unroll
        for (int p = 0; p < 16; p++) s += g_bp[(size_t)p * (B_ * R_ * R_) + i];
        g_b[i] = s;
    }
}

// ======================= shared fragment compute =======================
// One 16-wide k-step for one warp: A frags from Ahi/Alo (stride AST), B frags
// from Bhi/Blo (stride AST), 4 n-tiles, 3-term split accumulation.
template <int AST>
__device__ __forceinline__ void mma_kstep(const uint16_t* __restrict__ Ahi,
                                          const uint16_t* __restrict__ Alo,
                                          const uint16_t* __restrict__ Bhi,
                                          const uint16_t* __restrict__ Blo,
                                          int wrow, int g, int t4, int k16,
                                          float acc[4][4]) {
    uint32_t ah[4], al[4];
    int r0 = (wrow + g) * AST, r1 = (wrow + g + 8) * AST;
    int c0 = k16 + t4 * 2;
    ah[0] = *(const uint32_t*)&Ahi[r0 + c0];
    ah[1] = *(const uint32_t*)&Ahi[r1 + c0];
    ah[2] = *(const uint32_t*)&Ahi[r0 + c0 + 8];
    ah[3] = *(const uint32_t*)&Ahi[r1 + c0 + 8];
    al[0] = *(const uint32_t*)&Alo[r0 + c0];
    al[1] = *(const uint32_t*)&Alo[r1 + c0];
    al[2] = *(const uint32_t*)&Alo[r0 + c0 + 8];
    al[3] = *(const uint32_t*)&Alo[r1 + c0 + 8];
#pragma unroll
    for (int j = 0; j < 4; j++) {
        int nb = (j * 8 + g) * AST;
        uint32_t bh0 = *(const uint32_t*)&Bhi[nb + c0];
        uint32_t bh1 = *(const uint32_t*)&Bhi[nb + c0 + 8];
        uint32_t bl0 = *(const uint32_t*)&Blo[nb + c0];
        uint32_t bl1 = *(const uint32_t*)&Blo[nb + c0 + 8];
        mma16816(acc[j], ah, bh0, bh1);   // hi*hi
        mma16816(acc[j], ah, bl0, bl1);   // hi*lo
        mma16816(acc[j], al, bh0, bh1);   // lo*hi
    }
}

__device__ __forceinline__ void epilogue(float acc[4][4], float* __restrict__ out,
                                         int wrow, int g, int t4) {
    // out = g_a[b][m0][0]; rows wrow+g and wrow+g+8; cols j*8 + t4*2
#pragma unroll
    for (int j = 0; j < 4; j++) {
        float2 e0 = {acc[j][0], acc[j][1]};
        float2 e1 = {acc[j][2], acc[j][3]};
        *(float2*)(out + (size_t)(wrow + g) * R_ + j * 8 + t4 * 2) = e0;
        *(float2*)(out + (size_t)(wrow + g + 8) * R_ + j * 8 + t4 * 2) = e1;
    }
}

// ======================= pass 1: a = x @ v =======================
// grid (M_/128, B_), 256 threads (8 warps x 16 rows). KT=64, stride 72.
#define KT1 64
#define AST1 72
__global__ void __launch_bounds__(256, 1)
hmma_xv_kernel(const float* __restrict__ x, const float* __restrict__ v) {
    __shared__ __align__(16) uint16_t Ahi[128 * AST1], Alo[128 * AST1];
    __shared__ __align__(16) uint16_t Bhi[R_ * AST1], Blo[R_ * AST1];

    int tid = threadIdx.x, wid = tid >> 5, lane = tid & 31;
    int g = lane >> 2, t4 = lane & 3, wrow = wid * 16;
    int b = blockIdx.y, m0 = blockIdx.x * 128;

    const float* xb = x + (size_t)b * M_ * N_;
    const float* vb = v + (size_t)b * N_ * R_;

    int arow = tid >> 4;        // 0..15, +16*i
    int aq   = tid & 15;        // float4 col group
    int bk   = tid >> 3;        // 0..31, +32*i (v k row)
    int brq  = tid & 7;         // v float4 r group

    float acc[4][4] = {};

    // prefetch chunk 0
    float4 px[8], pv[2];
#pragma unroll
    for (int i = 0; i < 8; i++)
        px[i] = *(const float4*)(xb + (size_t)(m0 + arow + 16 * i) * N_ + aq * 4);
#pragma unroll
    for (int i = 0; i < 2; i++)
        pv[i] = *(const float4*)(vb + (size_t)(bk + 32 * i) * R_ + brq * 4);

    for (int t = 0; t < N_ / KT1; t++) {
        // stage A: fp32 -> bf16 hi/lo
#pragma unroll
        for (int i = 0; i < 8; i++) {
            int row = arow + 16 * i, k = aq * 4;
            uint32_t h01 = pack2bf(px[i].x, px[i].y);
            uint32_t h23 = pack2bf(px[i].z, px[i].w);
            float hx = __uint_as_float(h01 << 16), hy = __uint_as_float(h01 & 0xFFFF0000u);
            float hz = __uint_as_float(h23 << 16), hw = __uint_as_float(h23 & 0xFFFF0000u);
            uint32_t l01 = pack2bf(px[i].x - hx, px[i].y - hy);
            uint32_t l23 = pack2bf(px[i].z - hz, px[i].w - hw);
            *(uint2*)&Ahi[row * AST1 + k] = make_uint2(h01, h23);
            *(uint2*)&Alo[row * AST1 + k] = make_uint2(l01, l23);
        }
        // stage B transposed: v[k][r] -> B[r][k]
#pragma unroll
        for (int i = 0; i < 2; i++) {
            int k = bk + 32 * i;
            float vals[4] = {pv[i].x, pv[i].y, pv[i].z, pv[i].w};
#pragma unroll
            for (int e = 0; e < 4; e++) {
                int r = brq * 4 + e;
                uint16_t h = cvt1(vals[e]);
                Bhi[r * AST1 + k] = h;
                Blo[r * AST1 + k] = cvt1(vals[e] - bf2f(h));
            }
        }
        __syncthreads();

        // prefetch next chunk
        if (t + 1 < N_ / KT1) {
            int kb = (t + 1) * KT1;
#pragma unroll
            for (int i = 0; i < 8; i++)
                px[i] = *(const float4*)(xb + (size_t)(m0 + arow + 16 * i) * N_ + kb + aq * 4);
#pragma unroll
            for (int i = 0; i < 2; i++)
                pv[i] = *(const float4*)(vb + (size_t)(kb + bk + 32 * i) * R_ + brq * 4);
        }

#pragma unroll
        for (int kk = 0; kk < KT1 / 16; kk++)
            mma_kstep<AST1>(Ahi, Alo, Bhi, Blo, wrow, g, t4, kk * 16, acc);
        __syncthreads();
    }

    epilogue(acc, g_a + ((size_t)b * M_ + m0) * R_, wrow, g, t4);
}

// ======================= pass 2: a = x^T @ u =======================
// grid (N_/128, B_), 256 threads. KT=32, stride 40; x transposed via fp32 stage.
#define KT2 32
#define AST2 40
__global__ void __launch_bounds__(256, 1)
hmma_xtu_kernel(const float* __restrict__ x, const float* __restrict__ u) {
    __shared__ __align__(16) uint16_t Ahi[128 * AST2], Alo[128 * AST2];
    __shared__ __align__(16) uint16_t Bhi[R_ * AST2], Blo[R_ * AST2];
    __shared__ __align__(16) float stage[KT2][132];

    int tid = threadIdx.x, wid = tid >> 5, lane = tid & 31;
    int g = lane >> 2, t4 = lane & 3, wrow = wid * 16;
    int b = blockIdx.y, n0 = blockIdx.x * 128;

    const float* xb = x + (size_t)b * M_ * N_;
    const float* ub = u + (size_t)b * M_ * R_;

    int srow = tid >> 5;        // 0..7, stage k-row base +8*i
    int sq   = tid & 31;        // stage float4 col
    int bk   = tid >> 3;        // u k row
    int brq  = tid & 7;

    int an   = tid >> 1;        // transposed-convert output row (n), 0..127
    int ah_  = tid & 1;         // half of k range

    float acc[4][4] = {};

    float4 px[4], pu;
#pragma unroll
    for (int i = 0; i < 4; i++)
        px[i] = *(const float4*)(xb + (size_t)(srow + 8 * i) * N_ + n0 + sq * 4);
    pu = *(const float4*)(ub + (size_t)bk * R_ + brq * 4);

    for (int t = 0; t < N_ / KT2; t++) {
        // stage fp32 x chunk [32 k][128 n]
#pragma unroll
        for (int i = 0; i < 4; i++)
            *(float4*)&stage[srow + 8 * i][sq * 4] = px[i];
        // stage B: u[k][r] -> B[r][k]
        {
            float vals[4] = {pu.x, pu.y, pu.z, pu.w};
#pragma unroll
            for (int e = 0; e < 4; e++) {
                int r = brq * 4 + e;
                uint16_t h = cvt1(vals[e]);
                Bhi[r * AST2 + bk] = h;
                Blo[r * AST2 + bk] = cvt1(vals[e] - bf2f(h));
            }
        }
        __syncthreads();
        // transposed convert: A[n][k] bf16 hi/lo
#pragma unroll
        for (int j = 0; j < 4; j++) {
            int k0 = ah_ * 16 + j * 4;
            float a0 = stage[k0 + 0][an];
            float a1 = stage[k0 + 1][an];
            float a2 = stage[k0 + 2][an];
            float a3 = stage[k0 + 3][an];
            uint32_t h01 = pack2bf(a0, a1);
            uint32_t h23 = pack2bf(a2, a3);
            float hx = __uint_as_float(h01 << 16), hy = __uint_as_float(h01 & 0xFFFF0000u);
            float hz = __uint_as_float(h23 << 16), hw = __uint_as_float(h23 & 0xFFFF0000u);
            uint32_t l01 = pack2bf(a0 - hx, a1 - hy);
            uint32_t l23 = pack2bf(a2 - hz, a3 - hw);
            *(uint2*)&Ahi[an * AST2 + k0] = make_uint2(h01, h23);
            *(uint2*)&Alo[an * AST2 + k0] = make_uint2(l01, l23);
        }
        __syncthreads();

        if (t + 1 < N_ / KT2) {
            int mb = (t + 1) * KT2;
#pragma unroll
            for (int i = 0; i < 4; i++)
                px[i] = *(const float4*)(xb + (size_t)(mb + srow + 8 * i) * N_ + n0 + sq * 4);
            pu = *(const float4*)(ub + (size_t)(mb + bk) * R_ + brq * 4);
        }

#pragma unroll
        for (int kk = 0; kk < KT2 / 16; kk++)
            mma_kstep<AST2>(Ahi, Alo, Bhi, Blo, wrow, g, t4, kk * 16, acc);
        __syncthreads();
    }

    epilogue(acc, g_a + ((size_t)b * M_ + n0) * R_, wrow, g, t4);
}

// ======================= per-row Gauss-Seidel CD =======================
// grid (M_/64, B_), 64 threads. One row per thread, fully in registers.
__global__ void cd_kernel(const float* __restrict__ uin, float* __restrict__ uout,
                          float l1, float l2) {
    __shared__ float bs[R_][R_];
    __shared__ float inv[R_];
    int b = blockIdx.y, tid = threadIdx.x;
    {
        const float4* src = (const float4*)(g_b + (size_t)b * R_ * R_);
        float4* dst = (float4*)&bs[0][0];
#pragma unroll
        for (int i = 0; i < 4; i++) dst[tid + 64 * i] = src[tid + 64 * i];
    }
    __syncthreads();
    if (tid < R_) inv[tid] = 1.0f / (bs[tid][tid] + l2 + EPSC);

    int m = blockIdx.x * 64 + tid;
    const float* ar = g_a + ((size_t)b * M_ + m) * R_;
    const float* ur = uin + ((size_t)b * M_ + m) * R_;
    float areg[R_], ureg[R_];
#pragma unroll
    for (int i = 0; i < 8; i++) {
        float4 t = *(const float4*)(ar + i * 4);
        areg[4 * i + 0] = t.x; areg[4 * i + 1] = t.y; areg[4 * i + 2] = t.z; areg[4 * i + 3] = t.w;
        float4 t2 = *(const float4*)(ur + i * 4);
        ureg[4 * i + 0] = t2.x; ureg[4 * i + 1] = t2.y; ureg[4 * i + 2] = t2.z; ureg[4 * i + 3] = t2.w;
    }
    __syncthreads();

#pragma unroll
    for (int r = 0; r < R_; r++) {
        float brr = bs[r][r];
        float d0 = 0.f, d1 = 0.f, d2 = 0.f, d3 = 0.f;
#pragma unroll
        for (int k = 0; k < R_; k += 4) {
            d0 += ureg[k + 0] * bs[k + 0][r];
            d1 += ureg[k + 1] * bs[k + 1][r];
            d2 += ureg[k + 2] * bs[k + 2][r];
            d3 += ureg[k + 3] * bs[k + 3][r];
        }
        float dot = (d0 + d1) + (d2 + d3);
        float z = areg[r] - (dot - ureg[r] * brr);
        float num = (z > l1) ? (z - l1) : ((z < -l1) ? (z + l1) : 0.0f);
        ureg[r] = (num + EPSC) * inv[r];
    }

    float* outr = uout + ((size_t)b * M_ + m) * R_;
#pragma unroll
    for (int i = 0; i < 8; i++) {
        float4 o = {ureg[4 * i + 0], ureg[4 * i + 1], ureg[4 * i + 2], ureg[4 * i + 3]};
        *(float4*)(outr + i * 4) = o;
    }
}

// ---------------------------------------------------------------------------
extern "C" void kernel_launch(void* const* d_in, const int* in_sizes, int n_in,
                              void* d_out, int out_size) {
    const float* x = (const float*)d_in[0];
    const float* u = (const float*)d_in[1];
    const float* v = (const float*)d_in[2];
    float* uout = (float*)d_out;
    float* vout = uout + (size_t)B_ * M_ * R_;

    dim3 gg(16, B_);
    dim3 gt(M_ / 128, B_);      // 16 x 8 = 128 CTAs
    dim3 gc(M_ / 64, B_);

    // Phase 1: update u using original v
    gram_partial_kernel<<<gg, 256>>>(v);
    reduce_b_kernel<<<32, 256>>>();
    hmma_xv_kernel<<<gt, 256>>>(x, v);
    cd_kernel<<<gc, 64>>>(u, uout, L1C, L2C);

    // Phase 2: update v using NEW u
    gram_partial_kernel<<<gg, 256>>>(uout);
    reduce_b_kernel<<<32, 256>>>();
    hmma_xtu_kernel<<<gt, 256>>>(x, uout);
    cd_kernel<<<gc, 64>>>(v, vout, L1C, L2C);
}